// round 6
// baseline (speedup 1.0000x reference)
#include <cuda_runtime.h>
#include <cuda_bf16.h>
#include <cstdint>
#include <cstddef>

// Problem constants
#define BATCH 64
#define NTOK  341
#define DMODEL 768
#define NHEAD 12
#define HDIM  64
#define QKVDIM 2304   // 3*DMODEL

// Scratch (device globals; no allocation allowed)
__device__ float g_qkv[(size_t)BATCH * NTOK * QKVDIM];   // [B, N, 3, H, hd]
__device__ float g_att[(size_t)BATCH * NTOK * DMODEL];   // [B, N, D]

// ---------------------------------------------------------------------------
// fp32 NT-GEMM with bias: C[m,n] = bias[n] + sum_k A[m,k]*B[n,k]
// 128x128 tile, BK=16, 256 threads, 8x8 micro-tile, register-staged
// double buffering. N and K divide the tiles exactly; M is predicated.
// ---------------------------------------------------------------------------
#define BM 128
#define BN 128
#define BKK 16

__global__ __launch_bounds__(256) void sgemm_nt_bias(
    const float* __restrict__ A, const float* __restrict__ B,
    const float* __restrict__ bias, float* __restrict__ C,
    int M, int Nn, int K)
{
    __shared__ float As[2][BKK][BM];
    __shared__ float Bs[2][BKK][BN];

    const int tid = threadIdx.x;
    const int tx = tid & 15;
    const int ty = tid >> 4;
    const int m0 = blockIdx.y * BM;
    const int n0 = blockIdx.x * BN;

    const int lr = tid >> 2;
    const int lk = (tid & 3) * 4;

    const int gmA0 = m0 + lr;
    const int gmA1 = m0 + lr + 64;
    const bool pA0 = gmA0 < M;
    const bool pA1 = gmA1 < M;
    const float* ApA0 = A + (size_t)(pA0 ? gmA0 : 0) * K + lk;
    const float* ApA1 = A + (size_t)(pA1 ? gmA1 : 0) * K + lk;
    const float* BpB0 = B + (size_t)(n0 + lr) * K + lk;
    const float* BpB1 = B + (size_t)(n0 + lr + 64) * K + lk;

    float acc[8][8];
#pragma unroll
    for (int i = 0; i < 8; i++)
#pragma unroll
        for (int j = 0; j < 8; j++) acc[i][j] = 0.f;

    const float4 z4 = make_float4(0.f, 0.f, 0.f, 0.f);

    {
        float4 a0 = pA0 ? *(const float4*)ApA0 : z4;
        float4 a1 = pA1 ? *(const float4*)ApA1 : z4;
        float4 b0 = *(const float4*)BpB0;
        float4 b1 = *(const float4*)BpB1;
        As[0][lk + 0][lr] = a0.x; As[0][lk + 1][lr] = a0.y;
        As[0][lk + 2][lr] = a0.z; As[0][lk + 3][lr] = a0.w;
        As[0][lk + 0][lr + 64] = a1.x; As[0][lk + 1][lr + 64] = a1.y;
        As[0][lk + 2][lr + 64] = a1.z; As[0][lk + 3][lr + 64] = a1.w;
        Bs[0][lk + 0][lr] = b0.x; Bs[0][lk + 1][lr] = b0.y;
        Bs[0][lk + 2][lr] = b0.z; Bs[0][lk + 3][lr] = b0.w;
        Bs[0][lk + 0][lr + 64] = b1.x; Bs[0][lk + 1][lr + 64] = b1.y;
        Bs[0][lk + 2][lr + 64] = b1.z; Bs[0][lk + 3][lr + 64] = b1.w;
    }
    __syncthreads();

    int cur = 0;
    for (int k0 = 0; k0 < K; k0 += BKK) {
        const int kn = k0 + BKK;
        float4 a0, a1, b0, b1;
        const bool more = kn < K;
        if (more) {
            a0 = pA0 ? *(const float4*)(ApA0 + kn) : z4;
            a1 = pA1 ? *(const float4*)(ApA1 + kn) : z4;
            b0 = *(const float4*)(BpB0 + kn);
            b1 = *(const float4*)(BpB1 + kn);
        }

#pragma unroll
        for (int k = 0; k < BKK; k++) {
            float4 av0 = *(const float4*)&As[cur][k][ty * 4];
            float4 av1 = *(const float4*)&As[cur][k][64 + ty * 4];
            float4 bv0 = *(const float4*)&Bs[cur][k][tx * 4];
            float4 bv1 = *(const float4*)&Bs[cur][k][64 + tx * 4];
            float a[8] = {av0.x, av0.y, av0.z, av0.w, av1.x, av1.y, av1.z, av1.w};
            float b[8] = {bv0.x, bv0.y, bv0.z, bv0.w, bv1.x, bv1.y, bv1.z, bv1.w};
#pragma unroll
            for (int i = 0; i < 8; i++)
#pragma unroll
                for (int j = 0; j < 8; j++)
                    acc[i][j] = fmaf(a[i], b[j], acc[i][j]);
        }

        if (more) {
            const int nxt = cur ^ 1;
            As[nxt][lk + 0][lr] = a0.x; As[nxt][lk + 1][lr] = a0.y;
            As[nxt][lk + 2][lr] = a0.z; As[nxt][lk + 3][lr] = a0.w;
            As[nxt][lk + 0][lr + 64] = a1.x; As[nxt][lk + 1][lr + 64] = a1.y;
            As[nxt][lk + 2][lr + 64] = a1.z; As[nxt][lk + 3][lr + 64] = a1.w;
            Bs[nxt][lk + 0][lr] = b0.x; Bs[nxt][lk + 1][lr] = b0.y;
            Bs[nxt][lk + 2][lr] = b0.z; Bs[nxt][lk + 3][lr] = b0.w;
            Bs[nxt][lk + 0][lr + 64] = b1.x; Bs[nxt][lk + 1][lr + 64] = b1.y;
            Bs[nxt][lk + 2][lr + 64] = b1.z; Bs[nxt][lk + 3][lr + 64] = b1.w;
            __syncthreads();
            cur = nxt;
        }
    }

    const float4 bb0 = *(const float4*)&bias[n0 + tx * 4];
    const float4 bb1 = *(const float4*)&bias[n0 + 64 + tx * 4];
#pragma unroll
    for (int i = 0; i < 8; i++) {
        const int row = (i < 4) ? (ty * 4 + i) : (64 + ty * 4 + (i - 4));
        const int gm = m0 + row;
        if (gm >= M) continue;
        float4 r0, r1;
        r0.x = acc[i][0] + bb0.x; r0.y = acc[i][1] + bb0.y;
        r0.z = acc[i][2] + bb0.z; r0.w = acc[i][3] + bb0.w;
        r1.x = acc[i][4] + bb1.x; r1.y = acc[i][5] + bb1.y;
        r1.z = acc[i][6] + bb1.z; r1.w = acc[i][7] + bb1.w;
        *(float4*)&C[(size_t)gm * Nn + n0 + tx * 4] = r0;
        *(float4*)&C[(size_t)gm * Nn + n0 + 64 + tx * 4] = r1;
    }
}

// ---------------------------------------------------------------------------
// Fused scale-causal attention. One CTA per (batch, head).
// K (row stride 65, conflict-free) and V fully resident in SMEM.
// Mask is a prefix: query q attends to keys [0, kv_len(q)).
// Warp handles 4 queries; scores via 4q x 4k register micro-tile;
// PV loop vectorized (float4 P per 4 keys, float2 V per key).
// ---------------------------------------------------------------------------
__device__ __forceinline__ int kv_len(int q) {
    if (q < 1)  return 341;   // CLS attends everywhere
    if (q < 5)  return 5;
    if (q < 21) return 21;
    if (q < 85) return 85;
    return 341;
}

#define KSTRIDE 65
// K region padded to multiple of 4 floats so Vs is 16B-aligned.
#define KREGION 22168
#define SCP 344            // score row stride (>=341, multiple of 8)
#define NGROUPS 86         // ceil(341/4)
#define ATTN_SMEM_FLOATS (KREGION + NTOK * HDIM + 32 * SCP + 8 * 256)
#define ATTN_SMEM_BYTES (ATTN_SMEM_FLOATS * 4)   // 228,192 B

__global__ __launch_bounds__(256) void attn_kernel(
    const float* __restrict__ qkv, float* __restrict__ out)
{
    const int bh = blockIdx.x;
    const int b = bh / NHEAD;
    const int h = bh % NHEAD;

    extern __shared__ float sm[];
    float* Ks = sm;                        // [341][65] (+3 pad)
    float* Vs = Ks + KREGION;              // [341][64], 16B-aligned
    float* Sc = Vs + NTOK * HDIM;          // [32][344]
    float* Qb = Sc + 32 * SCP;             // [8][4][64]

    const int tid = threadIdx.x;
    const int lane = tid & 31;
    const int w = tid >> 5;

    const size_t rowbase = (size_t)b * NTOK;
    for (int idx = tid; idx < NTOK * 16; idx += 256) {
        const int n = idx >> 4;
        const int c = (idx & 15) * 4;
        const size_t base = (rowbase + n) * QKVDIM + h * HDIM + c;
        float4 k4 = *(const float4*)(qkv + base + DMODEL);
        float4 v4 = *(const float4*)(qkv + base + 2 * DMODEL);
        Ks[n * KSTRIDE + c + 0] = k4.x;
        Ks[n * KSTRIDE + c + 1] = k4.y;
        Ks[n * KSTRIDE + c + 2] = k4.z;
        Ks[n * KSTRIDE + c + 3] = k4.w;
        *(float4*)(Vs + n * HDIM + c) = v4;
    }
    __syncthreads();

    const float scale = 0.125f;  // 64^-0.5
    float* Qw = Qb + w * 256;
    float* Sw = Sc + (w * 4) * SCP;

    for (int g = w; g < NGROUPS; g += 8) {
        const int q0 = g * 4;
        const int nq = (NTOK - q0 < 4) ? (NTOK - q0) : 4;

        int Lmax = 0;
#pragma unroll
        for (int qi = 0; qi < 4; qi++)
            if (qi < nq) { int l = kv_len(q0 + qi); Lmax = (l > Lmax) ? l : Lmax; }

        // stage 4 query vectors (scaled); zero-fill absent queries
#pragma unroll
        for (int qi = 0; qi < 4; qi++) {
            if (qi < nq) {
                const float* qp = qkv + (rowbase + q0 + qi) * QKVDIM + h * HDIM;
                Qw[qi * 64 + lane]      = qp[lane] * scale;
                Qw[qi * 64 + lane + 32] = qp[lane + 32] * scale;
            } else {
                Qw[qi * 64 + lane]      = 0.f;
                Qw[qi * 64 + lane + 32] = 0.f;
            }
        }
        __syncwarp();

        // scores: 4 queries x 4 keys per lane per chunk of 128 keys
        for (int kb = 0; kb < Lmax; kb += 128) {
            const int k0 = kb + lane;
            const float* kr0 = Ks + (size_t)(k0 +  0) * KSTRIDE;
            const float* kr1 = Ks + (size_t)(k0 + 32) * KSTRIDE;
            const float* kr2 = Ks + (size_t)(k0 + 64) * KSTRIDE;
            const float* kr3 = Ks + (size_t)(k0 + 96) * KSTRIDE;

            float acc[4][4];
#pragma unroll
            for (int qi = 0; qi < 4; qi++)
#pragma unroll
                for (int kk = 0; kk < 4; kk++) acc[qi][kk] = 0.f;

#pragma unroll 8
            for (int d = 0; d < 64; d++) {
                const float kv0 = kr0[d];
                const float kv1 = kr1[d];
                const float kv2 = kr2[d];
                const float kv3 = kr3[d];
#pragma unroll
                for (int qi = 0; qi < 4; qi++) {
                    const float qv = Qw[qi * 64 + d];
                    acc[qi][0] = fmaf(qv, kv0, acc[qi][0]);
                    acc[qi][1] = fmaf(qv, kv1, acc[qi][1]);
                    acc[qi][2] = fmaf(qv, kv2, acc[qi][2]);
                    acc[qi][3] = fmaf(qv, kv3, acc[qi][3]);
                }
            }
#pragma unroll
            for (int qi = 0; qi < 4; qi++) {
#pragma unroll
                for (int kk = 0; kk < 4; kk++) {
                    const int k = k0 + kk * 32;
                    if (k < Lmax) Sw[qi * SCP + k] = acc[qi][kk];
                }
            }
        }
        __syncwarp();

        // softmax per query (prefix Lq); zero tail [Lq, Lmax)
        float inv[4] = {0.f, 0.f, 0.f, 0.f};
#pragma unroll
        for (int qi = 0; qi < 4; qi++) {
            if (qi >= nq) continue;
            const int Lq = kv_len(q0 + qi);
            float* sr = Sw + qi * SCP;
            float mx = -1e30f;
            for (int k = lane; k < Lq; k += 32) mx = fmaxf(mx, sr[k]);
#pragma unroll
            for (int o = 16; o; o >>= 1) mx = fmaxf(mx, __shfl_xor_sync(0xffffffffu, mx, o));
            float s = 0.f;
            for (int k = lane; k < Lq; k += 32) {
                const float e = __expf(sr[k] - mx);
                sr[k] = e;
                s += e;
            }
#pragma unroll
            for (int o = 16; o; o >>= 1) s += __shfl_xor_sync(0xffffffffu, s, o);
            inv[qi] = 1.f / s;
            for (int k = Lq + lane; k < Lmax; k += 32) sr[k] = 0.f;
        }
        __syncwarp();

        // O = P @ V, 4 queries at once. Lane owns dims {2*lane, 2*lane+1}.
        // P loaded as float4 per query per 4 keys; V as float2 per key.
        float o0[4] = {0.f, 0.f, 0.f, 0.f};
        float o1[4] = {0.f, 0.f, 0.f, 0.f};
        const int L4 = Lmax & ~3;
        int k = 0;
        for (; k < L4; k += 4) {
            float4 p[4];
#pragma unroll
            for (int qi = 0; qi < 4; qi++)
                p[qi] = *(const float4*)&Sw[qi * SCP + k];
#pragma unroll
            for (int kk = 0; kk < 4; kk++) {
                const float2 v = *(const float2*)&Vs[(k + kk) * HDIM + 2 * lane];
#pragma unroll
                for (int qi = 0; qi < 4; qi++) {
                    const float pv = (kk == 0) ? p[qi].x : (kk == 1) ? p[qi].y
                                   : (kk == 2) ? p[qi].z : p[qi].w;
                    o0[qi] = fmaf(pv, v.x, o0[qi]);
                    o1[qi] = fmaf(pv, v.y, o1[qi]);
                }
            }
        }
        for (; k < Lmax; k++) {
            const float2 v = *(const float2*)&Vs[k * HDIM + 2 * lane];
#pragma unroll
            for (int qi = 0; qi < 4; qi++) {
                const float pv = Sw[qi * SCP + k];
                o0[qi] = fmaf(pv, v.x, o0[qi]);
                o1[qi] = fmaf(pv, v.y, o1[qi]);
            }
        }

#pragma unroll
        for (int qi = 0; qi < 4; qi++) {
            if (qi >= nq) continue;
            float* op = out + (rowbase + q0 + qi) * DMODEL + h * HDIM;
            float2 r;
            r.x = o0[qi] * inv[qi];
            r.y = o1[qi] * inv[qi];
            *(float2*)&op[2 * lane] = r;
        }
        __syncwarp();
    }
}

// ---------------------------------------------------------------------------
extern "C" void kernel_launch(void* const* d_in, const int* in_sizes, int n_in,
                              void* d_out, int out_size)
{
    const float* x      = (const float*)d_in[0];
    const float* qkv_w  = (const float*)d_in[1];
    const float* qkv_b  = (const float*)d_in[2];
    const float* proj_w = (const float*)d_in[3];
    const float* proj_b = (const float*)d_in[4];
    float* out = (float*)d_out;

    float* qkv_s = nullptr;
    float* att_s = nullptr;
    cudaGetSymbolAddress((void**)&qkv_s, g_qkv);
    cudaGetSymbolAddress((void**)&att_s, g_att);

    cudaFuncSetAttribute(attn_kernel,
                         cudaFuncAttributeMaxDynamicSharedMemorySize,
                         ATTN_SMEM_BYTES);

    const int M = BATCH * NTOK;        // 21824
    const int gy = (M + BM - 1) / BM;  // 171

    // 1) qkv = x @ qkv_w^T + qkv_b
    sgemm_nt_bias<<<dim3(QKVDIM / BN, gy), 256>>>(
        x, qkv_w, qkv_b, qkv_s, M, QKVDIM, DMODEL);

    // 2) fused scale-causal attention
    attn_kernel<<<BATCH * NHEAD, 256, ATTN_SMEM_BYTES>>>(qkv_s, att_s);

    // 3) out = att @ proj_w^T + proj_b
    sgemm_nt_bias<<<dim3(DMODEL / BN, gy), 256>>>(
        att_s, proj_w, proj_b, out, M, DMODEL, DMODEL);
}

// round 14
// speedup vs baseline: 1.5924x; 1.5924x over previous
#include <cuda_runtime.h>
#include <cuda_bf16.h>
#include <cstdint>
#include <cstddef>

// Problem constants
#define BATCH 64
#define NTOK  341
#define DMODEL 768
#define NHEAD 12
#define HDIM  64
#define QKVDIM 2304            // 3*DMODEL
#define MTOT (BATCH * NTOK)    // 21824
#define K2 1536                // operand storage: [hi(768) | lo(768)] bf16

// Scratch (device globals; no allocation allowed)
__device__ float g_qkv[(size_t)MTOT * QKVDIM];
__device__ float g_att[(size_t)MTOT * DMODEL];
__device__ __nv_bfloat16 g_x2[(size_t)MTOT * K2];      // x split hi|lo
__device__ __nv_bfloat16 g_w2[(size_t)QKVDIM * K2];    // qkv_w split
__device__ __nv_bfloat16 g_att2[(size_t)MTOT * K2];    // att split
__device__ __nv_bfloat16 g_pw2[(size_t)DMODEL * K2];   // proj_w split

// ===========================================================================
// Helpers (arch-neutral PTX only: ldmatrix sm_75+, mma.sync sm_80+, cp.async)
// ===========================================================================
__device__ __forceinline__ uint32_t smem_u32(const void* p) {
    uint32_t a;
    asm("{ .reg .u64 t; cvta.to.shared.u64 t, %1; cvt.u32.u64 %0, t; }"
        : "=r"(a) : "l"(p));
    return a;
}
__device__ __forceinline__ void cp_async16(uint32_t dst, const void* src) {
    asm volatile("cp.async.cg.shared.global [%0], [%1], 16;\n"
                 :: "r"(dst), "l"(src) : "memory");
}
#define CP_COMMIT() asm volatile("cp.async.commit_group;\n" ::: "memory")
#define CP_WAIT(n)  asm volatile("cp.async.wait_group %0;\n" :: "n"(n) : "memory")

__device__ __forceinline__ void ldsm_x4(uint32_t* r, uint32_t addr) {
    asm volatile("ldmatrix.sync.aligned.m8n8.x4.shared.b16 {%0,%1,%2,%3}, [%4];\n"
                 : "=r"(r[0]), "=r"(r[1]), "=r"(r[2]), "=r"(r[3]) : "r"(addr));
}
__device__ __forceinline__ void mma16816(float* d, const uint32_t* a,
                                         uint32_t b0, uint32_t b1) {
    asm volatile(
        "mma.sync.aligned.m16n8k16.row.col.f32.bf16.bf16.f32 "
        "{%0,%1,%2,%3},{%4,%5,%6,%7},{%8,%9},{%0,%1,%2,%3};\n"
        : "+f"(d[0]), "+f"(d[1]), "+f"(d[2]), "+f"(d[3])
        : "r"(a[0]), "r"(a[1]), "r"(a[2]), "r"(a[3]), "r"(b0), "r"(b1));
}

// ===========================================================================
// fp32 -> bf16 hi|lo split: src [R][768] f32 -> dst [R][1536] bf16
// ===========================================================================
__global__ __launch_bounds__(256) void cvt_split(
    const float* __restrict__ src, __nv_bfloat16* __restrict__ dst, int total4)
{
    int i = blockIdx.x * blockDim.x + threadIdx.x;
    if (i >= total4) return;
    const int r = i / 192;
    const int c = (i - r * 192) * 4;
    float4 v = *(const float4*)(src + (size_t)r * DMODEL + c);
    __nv_bfloat16 h0 = __float2bfloat16(v.x);
    __nv_bfloat16 h1 = __float2bfloat16(v.y);
    __nv_bfloat16 h2 = __float2bfloat16(v.z);
    __nv_bfloat16 h3 = __float2bfloat16(v.w);
    __nv_bfloat16 l0 = __float2bfloat16(v.x - __bfloat162float(h0));
    __nv_bfloat16 l1 = __float2bfloat16(v.y - __bfloat162float(h1));
    __nv_bfloat16 l2 = __float2bfloat16(v.z - __bfloat162float(h2));
    __nv_bfloat16 l3 = __float2bfloat16(v.w - __bfloat162float(h3));
    ushort4 hv = make_ushort4(__bfloat16_as_ushort(h0), __bfloat16_as_ushort(h1),
                              __bfloat16_as_ushort(h2), __bfloat16_as_ushort(h3));
    ushort4 lv = make_ushort4(__bfloat16_as_ushort(l0), __bfloat16_as_ushort(l1),
                              __bfloat16_as_ushort(l2), __bfloat16_as_ushort(l3));
    *(ushort4*)(dst + (size_t)r * K2 + c)          = hv;
    *(ushort4*)(dst + (size_t)r * K2 + DMODEL + c) = lv;
}

// ===========================================================================
// mma.sync bf16 NT-GEMM w/ bias, 3-term hi/lo emulation of fp32:
//   C = Ah*Bh + Al*Bh + Ah*Bl (+bias)   (dropped Al*Bl ~2^-16 rel)
// CTA 128x128, 8 warps (warp tile 32x64), BK=64 chunks (36 term-mapped),
// cp.async double-buffered smem, padded rows (144B stride, LDSM
// conflict-free), ldmatrix fragments + m16n8k16 bf16 mma.
// ===========================================================================
#define ASTR 72                       // bf16 elems per smem row (144 B)
#define ABUF_B (128 * ASTR * 2)       // 18432 B per A (or B) buffer
#define CHUNK_B (2 * ABUF_B)          // A+B per stage = 36864 B
#define GEMM_SMEM (2 * CHUNK_B)       // 73728 B
#define NCHUNKS 36                    // 3 terms x 12 chunks of 64

__global__ __launch_bounds__(256) void mma_gemm_nt_bias(
    const __nv_bfloat16* __restrict__ A, const __nv_bfloat16* __restrict__ B,
    const float* __restrict__ bias, float* __restrict__ C, int M, int Nn)
{
    extern __shared__ char sm[];
    const uint32_t smBase = smem_u32(sm);
    const int tid = threadIdx.x;
    const int wid = tid >> 5;
    const int lane = tid & 31;
    const int m0 = blockIdx.y * 128;
    const int n0c = blockIdx.x * 128;
    const int warpM = wid & 3;        // 4 m-positions of 32
    const int warpN = wid >> 2;       // 2 n-positions of 64

    float acc[16][4];
#pragma unroll
    for (int i = 0; i < 16; i++)
#pragma unroll
        for (int j = 0; j < 4; j++) acc[i][j] = 0.f;

    // ---- async stage of chunk c into buffer c&1 ----
    auto issue = [&](int c) {
        const int term = c / 12;
        const int kk = c - term * 12;
        const size_t aoff = (size_t)kk * 64 + ((term == 1) ? DMODEL : 0);
        const size_t boff = (size_t)kk * 64 + ((term == 2) ? DMODEL : 0);
        const uint32_t dstA = smBase + (uint32_t)(c & 1) * CHUNK_B;
        const uint32_t dstB = dstA + ABUF_B;
#pragma unroll
        for (int i = 0; i < 4; i++) {
            const int idx = tid + i * 256;
            const int r = idx >> 3;
            const int g = idx & 7;
            int gr = m0 + r; if (gr >= M) gr = M - 1;   // clamp; never stored
            cp_async16(dstA + (uint32_t)(r * 144 + g * 16),
                       A + (size_t)gr * K2 + aoff + g * 8);
            cp_async16(dstB + (uint32_t)(r * 144 + g * 16),
                       B + (size_t)(n0c + r) * K2 + boff + g * 8);
        }
        CP_COMMIT();
    };

    issue(0);
    for (int c = 0; c < NCHUNKS; c++) {
        if (c + 1 < NCHUNKS) { issue(c + 1); CP_WAIT(1); }
        else                 { CP_WAIT(0); }
        __syncthreads();

        const uint32_t aBase = smBase + (uint32_t)(c & 1) * CHUNK_B;
        const uint32_t bBase = aBase + ABUF_B;

#pragma unroll
        for (int ks = 0; ks < 4; ks++) {            // four k16 steps in BK=64
            const int k0 = ks * 16;
            uint32_t afr[2][4];
#pragma unroll
            for (int mt = 0; mt < 2; mt++) {
                const int row = warpM * 32 + mt * 16 + (lane & 15);
                const int col = k0 + (lane >> 4) * 8;
                ldsm_x4(afr[mt], aBase + (uint32_t)(row * 144 + col * 2));
            }
            uint32_t bfr[4][4];
#pragma unroll
            for (int p = 0; p < 4; p++) {           // pairs of n8 tiles
                const int nrow = warpN * 64 + p * 16 + (lane & 7) + ((lane >> 4) << 3);
                const int col = k0 + (((lane >> 3) & 1) << 3);
                ldsm_x4(bfr[p], bBase + (uint32_t)(nrow * 144 + col * 2));
            }
#pragma unroll
            for (int mt = 0; mt < 2; mt++)
#pragma unroll
                for (int nt = 0; nt < 8; nt++) {
                    const int p = nt >> 1, w2c = nt & 1;
                    mma16816(acc[mt * 8 + nt], afr[mt],
                             bfr[p][w2c * 2], bfr[p][w2c * 2 + 1]);
                }
        }
        __syncthreads();
    }

    // ---- epilogue: D fragment -> gmem with bias ----
    const int tg = lane >> 2;          // groupID: row within tile
    const int tig = lane & 3;          // thread-in-group: col pair
#pragma unroll
    for (int mt = 0; mt < 2; mt++) {
#pragma unroll
        for (int nt = 0; nt < 8; nt++) {
            const float* a4 = acc[mt * 8 + nt];
            const int mlo = m0 + warpM * 32 + mt * 16 + tg;
            const int n = n0c + warpN * 64 + nt * 8 + tig * 2;
            const float2 bb = *(const float2*)&bias[n];
            if (mlo < M) {
                float2 v = make_float2(a4[0] + bb.x, a4[1] + bb.y);
                *(float2*)&C[(size_t)mlo * Nn + n] = v;
            }
            const int mhi = mlo + 8;
            if (mhi < M) {
                float2 v = make_float2(a4[2] + bb.x, a4[3] + bb.y);
                *(float2*)&C[(size_t)mhi * Nn + n] = v;
            }
        }
    }
}

// ===========================================================================
// Fused scale-causal attention (verified passing version, unchanged)
// ===========================================================================
__device__ __forceinline__ int kv_len(int q) {
    if (q < 1)  return 341;
    if (q < 5)  return 5;
    if (q < 21) return 21;
    if (q < 85) return 85;
    return 341;
}

#define KSTRIDE 65
#define KREGION 22168
#define SCP 344
#define NGROUPS 86
#define ATTN_SMEM_FLOATS (KREGION + NTOK * HDIM + 32 * SCP + 8 * 256)
#define ATTN_SMEM_BYTES (ATTN_SMEM_FLOATS * 4)

__global__ __launch_bounds__(256) void attn_kernel(
    const float* __restrict__ qkv, float* __restrict__ out)
{
    const int bh = blockIdx.x;
    const int b = bh / NHEAD;
    const int h = bh % NHEAD;

    extern __shared__ float smf[];
    float* Ks = smf;
    float* Vs = Ks + KREGION;
    float* Sc = Vs + NTOK * HDIM;
    float* Qb = Sc + 32 * SCP;

    const int tid = threadIdx.x;
    const int lane = tid & 31;
    const int w = tid >> 5;

    const size_t rowbase = (size_t)b * NTOK;
    for (int idx = tid; idx < NTOK * 16; idx += 256) {
        const int n = idx >> 4;
        const int c = (idx & 15) * 4;
        const size_t base = (rowbase + n) * QKVDIM + h * HDIM + c;
        float4 k4 = *(const float4*)(qkv + base + DMODEL);
        float4 v4 = *(const float4*)(qkv + base + 2 * DMODEL);
        Ks[n * KSTRIDE + c + 0] = k4.x;
        Ks[n * KSTRIDE + c + 1] = k4.y;
        Ks[n * KSTRIDE + c + 2] = k4.z;
        Ks[n * KSTRIDE + c + 3] = k4.w;
        *(float4*)(Vs + n * HDIM + c) = v4;
    }
    __syncthreads();

    const float scale = 0.125f;
    float* Qw = Qb + w * 256;
    float* Sw = Sc + (w * 4) * SCP;

    for (int g = w; g < NGROUPS; g += 8) {
        const int q0 = g * 4;
        const int nq = (NTOK - q0 < 4) ? (NTOK - q0) : 4;

        int Lmax = 0;
#pragma unroll
        for (int qi = 0; qi < 4; qi++)
            if (qi < nq) { int l = kv_len(q0 + qi); Lmax = (l > Lmax) ? l : Lmax; }

#pragma unroll
        for (int qi = 0; qi < 4; qi++) {
            if (qi < nq) {
                const float* qp = qkv + (rowbase + q0 + qi) * QKVDIM + h * HDIM;
                Qw[qi * 64 + lane]      = qp[lane] * scale;
                Qw[qi * 64 + lane + 32] = qp[lane + 32] * scale;
            } else {
                Qw[qi * 64 + lane]      = 0.f;
                Qw[qi * 64 + lane + 32] = 0.f;
            }
        }
        __syncwarp();

        for (int kb = 0; kb < Lmax; kb += 128) {
            const int k0 = kb + lane;
            const float* kr0 = Ks + (size_t)(k0 +  0) * KSTRIDE;
            const float* kr1 = Ks + (size_t)(k0 + 32) * KSTRIDE;
            const float* kr2 = Ks + (size_t)(k0 + 64) * KSTRIDE;
            const float* kr3 = Ks + (size_t)(k0 + 96) * KSTRIDE;

            float accs[4][4];
#pragma unroll
            for (int qi = 0; qi < 4; qi++)
#pragma unroll
                for (int kk = 0; kk < 4; kk++) accs[qi][kk] = 0.f;

#pragma unroll 8
            for (int d = 0; d < 64; d++) {
                const float kv0 = kr0[d];
                const float kv1 = kr1[d];
                const float kv2 = kr2[d];
                const float kv3 = kr3[d];
#pragma unroll
                for (int qi = 0; qi < 4; qi++) {
                    const float qv = Qw[qi * 64 + d];
                    accs[qi][0] = fmaf(qv, kv0, accs[qi][0]);
                    accs[qi][1] = fmaf(qv, kv1, accs[qi][1]);
                    accs[qi][2] = fmaf(qv, kv2, accs[qi][2]);
                    accs[qi][3] = fmaf(qv, kv3, accs[qi][3]);
                }
            }
#pragma unroll
            for (int qi = 0; qi < 4; qi++) {
#pragma unroll
                for (int kk = 0; kk < 4; kk++) {
                    const int k = k0 + kk * 32;
                    if (k < Lmax) Sw[qi * SCP + k] = accs[qi][kk];
                }
            }
        }
        __syncwarp();

        float inv[4] = {0.f, 0.f, 0.f, 0.f};
#pragma unroll
        for (int qi = 0; qi < 4; qi++) {
            if (qi >= nq) continue;
            const int Lq = kv_len(q0 + qi);
            float* sr = Sw + qi * SCP;
            float mx = -1e30f;
            for (int k = lane; k < Lq; k += 32) mx = fmaxf(mx, sr[k]);
#pragma unroll
            for (int o = 16; o; o >>= 1) mx = fmaxf(mx, __shfl_xor_sync(0xffffffffu, mx, o));
            float s = 0.f;
            for (int k = lane; k < Lq; k += 32) {
                const float e = __expf(sr[k] - mx);
                sr[k] = e;
                s += e;
            }
#pragma unroll
            for (int o = 16; o; o >>= 1) s += __shfl_xor_sync(0xffffffffu, s, o);
            inv[qi] = 1.f / s;
            for (int k = Lq + lane; k < Lmax; k += 32) sr[k] = 0.f;
        }
        __syncwarp();

        float o0[4] = {0.f, 0.f, 0.f, 0.f};
        float o1[4] = {0.f, 0.f, 0.f, 0.f};
        const int L4 = Lmax & ~3;
        int k = 0;
        for (; k < L4; k += 4) {
            float4 p[4];
#pragma unroll
            for (int qi = 0; qi < 4; qi++)
                p[qi] = *(const float4*)&Sw[qi * SCP + k];
#pragma unroll
            for (int kk = 0; kk < 4; kk++) {
                const float2 v = *(const float2*)&Vs[(k + kk) * HDIM + 2 * lane];
#pragma unroll
                for (int qi = 0; qi < 4; qi++) {
                    const float pv = (kk == 0) ? p[qi].x : (kk == 1) ? p[qi].y
                                   : (kk == 2) ? p[qi].z : p[qi].w;
                    o0[qi] = fmaf(pv, v.x, o0[qi]);
                    o1[qi] = fmaf(pv, v.y, o1[qi]);
                }
            }
        }
        for (; k < Lmax; k++) {
            const float2 v = *(const float2*)&Vs[k * HDIM + 2 * lane];
#pragma unroll
            for (int qi = 0; qi < 4; qi++) {
                const float pv = Sw[qi * SCP + k];
                o0[qi] = fmaf(pv, v.x, o0[qi]);
                o1[qi] = fmaf(pv, v.y, o1[qi]);
            }
        }

#pragma unroll
        for (int qi = 0; qi < 4; qi++) {
            if (qi >= nq) continue;
            float* op = out + (rowbase + q0 + qi) * DMODEL + h * HDIM;
            float2 r;
            r.x = o0[qi] * inv[qi];
            r.y = o1[qi] * inv[qi];
            *(float2*)&op[2 * lane] = r;
        }
        __syncwarp();
    }
}

// ===========================================================================
extern "C" void kernel_launch(void* const* d_in, const int* in_sizes, int n_in,
                              void* d_out, int out_size)
{
    const float* x      = (const float*)d_in[0];
    const float* qkv_w  = (const float*)d_in[1];
    const float* qkv_b  = (const float*)d_in[2];
    const float* proj_w = (const float*)d_in[3];
    const float* proj_b = (const float*)d_in[4];
    float* out = (float*)d_out;

    float *qkv_s = nullptr, *att_s = nullptr;
    __nv_bfloat16 *x2 = nullptr, *w2 = nullptr, *att2 = nullptr, *pw2 = nullptr;
    cudaGetSymbolAddress((void**)&qkv_s, g_qkv);
    cudaGetSymbolAddress((void**)&att_s, g_att);
    cudaGetSymbolAddress((void**)&x2,  g_x2);
    cudaGetSymbolAddress((void**)&w2,  g_w2);
    cudaGetSymbolAddress((void**)&att2, g_att2);
    cudaGetSymbolAddress((void**)&pw2, g_pw2);

    cudaFuncSetAttribute(attn_kernel,
                         cudaFuncAttributeMaxDynamicSharedMemorySize, ATTN_SMEM_BYTES);
    cudaFuncSetAttribute(mma_gemm_nt_bias,
                         cudaFuncAttributeMaxDynamicSharedMemorySize, GEMM_SMEM);

    // splits: x, qkv_w, proj_w
    {
        const int t_x = MTOT * 192;
        const int t_w = QKVDIM * 192;
        const int t_p = DMODEL * 192;
        cvt_split<<<(t_x + 255) / 256, 256>>>(x, x2, t_x);
        cvt_split<<<(t_w + 255) / 256, 256>>>(qkv_w, w2, t_w);
        cvt_split<<<(t_p + 255) / 256, 256>>>(proj_w, pw2, t_p);
    }

    const int gy = (MTOT + 127) / 128;   // 171

    // 1) qkv = x @ qkv_w^T + qkv_b   (mma.sync bf16, 3-term emulation)
    mma_gemm_nt_bias<<<dim3(QKVDIM / 128, gy), 256, GEMM_SMEM>>>(
        x2, w2, qkv_b, qkv_s, MTOT, QKVDIM);

    // 2) fused scale-causal attention
    attn_kernel<<<BATCH * NHEAD, 256, ATTN_SMEM_BYTES>>>(qkv_s, att_s);

    // split attention output
    {
        const int t_a = MTOT * 192;
        cvt_split<<<(t_a + 255) / 256, 256>>>(att_s, att2, t_a);
    }

    // 3) out = att @ proj_w^T + proj_b
    mma_gemm_nt_bias<<<dim3(DMODEL / 128, gy), 256, GEMM_SMEM>>>(
        att2, pw2, proj_b, out, MTOT, DMODEL);
}